// round 1
// baseline (speedup 1.0000x reference)
#include <cuda_runtime.h>
#include <math.h>

// Problem dims
#define T_LEN 512
#define M_    4
#define N_    48
#define DIN   52          // M + N
#define H1_   4160
#define HID_  2320
#define G3_   6960        // 3 * HID
#define H2_   768

#define NBLK  148
#define NTHR  512
#define NWARP 16

// ---------------- device scratch (static: allocation-free) ----------------
__device__ float g_h[2][HID_];
__device__ float g_l1[H1_];
__device__ float g_gi[G3_];
__device__ float g_gh[G3_];
__device__ float g_l2[H2_];
__device__ unsigned g_bar_count;
__device__ unsigned g_bar_gen;

// ---------------- grid barrier (persistent-kernel, all blocks resident) ---
__device__ __forceinline__ void grid_barrier() {
    __syncthreads();
    if (threadIdx.x == 0) {
        __threadfence();  // release: publish this block's writes
        unsigned gen = *((volatile unsigned*)&g_bar_gen);
        if (atomicAdd(&g_bar_count, 1u) == gridDim.x - 1u) {
            atomicExch(&g_bar_count, 0u);
            __threadfence();
            *((volatile unsigned*)&g_bar_gen) = gen + 1u;
        } else {
            while (*((volatile unsigned*)&g_bar_gen) == gen) { }
        }
        __threadfence();  // acquire: gpu-scope fence -> CCTL.IVALL (invalidate L1D)
    }
    __syncthreads();
}

// ---------------- warp-per-row dot (float4 lane-strided) ------------------
__device__ __forceinline__ float warp_dot(const float* __restrict__ w,
                                          const float* __restrict__ x,
                                          int n4) {
    const float4* w4 = (const float4*)w;
    const float4* x4 = (const float4*)x;
    int lane = threadIdx.x & 31;
    float acc = 0.f;
#pragma unroll 4
    for (int c = lane; c < n4; c += 32) {
        float4 a = w4[c];
        float4 b = x4[c];
        acc = fmaf(a.x, b.x, acc);
        acc = fmaf(a.y, b.y, acc);
        acc = fmaf(a.z, b.z, acc);
        acc = fmaf(a.w, b.w, acc);
    }
#pragma unroll
    for (int o = 16; o; o >>= 1) acc += __shfl_down_sync(0xffffffffu, acc, o);
    return acc;
}

__device__ __forceinline__ float sigmoidf_(float x) {
    return 1.f / (1.f + __expf(-x));
}

// ---------------- persistent kernel ---------------------------------------
__global__ void __launch_bounds__(NTHR, 1)
kalmannet_kernel(const float* __restrict__ A,   const float* __restrict__ C,
                 const float* __restrict__ x0,  const float* __restrict__ h0,
                 const float* __restrict__ y,   const float* __restrict__ W1,
                 const float* __restrict__ b1,  const float* __restrict__ Wih,
                 const float* __restrict__ Whh, const float* __restrict__ bih,
                 const float* __restrict__ bhh, const float* __restrict__ W2,
                 const float* __restrict__ b2,  const float* __restrict__ W3,
                 const float* __restrict__ b3,  float* __restrict__ out) {
    const int tid  = threadIdx.x;
    const int bid  = blockIdx.x;
    const int wid  = tid >> 5;
    const int lane = tid & 31;

    __shared__ __align__(16) float s_vec[H1_];   // l1 staging (phase 2)
    __shared__ __align__(16) float s_h[HID_];    // h / h_new
    __shared__ __align__(16) float s_l2[H2_];    // block 0 only
    __shared__ __align__(16) float s_knet[56];   // 52 used, padded to f4
    __shared__ float s_dy[N_];
    __shared__ float s_xprior[M_], s_xpost[M_], s_xprev[M_], s_xacc[M_];

    for (int t = 0; t < T_LEN; ++t) {
        const float* hsrc = (t == 0) ? h0 : g_h[t & 1];

        // ================= Phase 1 =================
        if (bid != 0) {
            // blocks 1..147: gh = Whh @ h + bhh
            for (int i = tid; i < HID_; i += NTHR) s_h[i] = hsrc[i];
            __syncthreads();
            int gw = (bid - 1) * NWARP + wid;
            for (int r = gw; r < G3_; r += (NBLK - 1) * NWARP) {
                float v = warp_dot(Whh + (size_t)r * HID_, s_h, HID_ / 4);
                if (lane == 0) g_gh[r] = v + bhh[r];
            }
        } else {
            // ---- block 0: serial small chain ----
            if (t == 0) {
                if (tid < M_) { s_xpost[tid] = x0[tid]; s_xprev[tid] = x0[tid]; }
                __syncthreads();
            } else {
                // finish step t-1: kg = (W3 @ l2 + b3)/1e4 ; x_post = x_prior + kg @ dy
                for (int i = tid; i < H2_; i += NTHR) s_l2[i] = g_l2[i];
                if (tid < M_) s_xacc[tid] = 0.f;
                __syncthreads();
                for (int r = wid; r < M_ * N_; r += NWARP) {
                    float v = warp_dot(W3 + (size_t)r * H2_, s_l2, H2_ / 4);
                    if (lane == 0) {
                        v = (v + b3[r]) * 1e-4f;
                        atomicAdd(&s_xacc[r / N_], v * s_dy[r % N_]);
                    }
                }
                __syncthreads();
                if (tid < M_) {
                    float xp = s_xprior[tid] + s_xacc[tid];
                    s_xprev[tid] = s_xprior[tid];
                    s_xpost[tid] = xp;
                    out[tid * T_LEN + (t - 1)] = xp;
                }
                __syncthreads();
            }
            // x_prior = A @ x_post
            if (tid < M_) {
                float acc = 0.f;
#pragma unroll
                for (int k = 0; k < M_; ++k) acc = fmaf(A[tid * M_ + k], s_xpost[k], acc);
                s_xprior[tid] = acc;
            }
            __syncthreads();
            // dy, dx, normalized knet_in (warp 0)
            if (wid == 0) {
                for (int j = lane; j < N_; j += 32) {
                    float m = C[j * (M_ + 1) + M_];   // * 1.0 appended
#pragma unroll
                    for (int k = 0; k < M_; ++k) m = fmaf(C[j * (M_ + 1) + k], s_xprior[k], m);
                    s_dy[j] = y[j * T_LEN + t] - m;
                }
                __syncwarp();
                float sq = 0.f;
                for (int j = lane; j < N_; j += 32) sq += s_dy[j] * s_dy[j];
#pragma unroll
                for (int o = 16; o; o >>= 1) sq += __shfl_down_sync(0xffffffffu, sq, o);
                sq = __shfl_sync(0xffffffffu, sq, 0);
                float inv = 1.f / fmaxf(sqrtf(sq), 1e-12f);
                for (int j = lane; j < N_; j += 32) s_knet[j] = s_dy[j] * inv;

                float dx = (lane < M_) ? (s_xpost[lane] - s_xprev[lane]) : 0.f;
                float sq2 = dx * dx;
#pragma unroll
                for (int o = 16; o; o >>= 1) sq2 += __shfl_down_sync(0xffffffffu, sq2, o);
                sq2 = __shfl_sync(0xffffffffu, sq2, 0);
                float inv2 = 1.f / fmaxf(sqrtf(sq2), 1e-12f);
                if (lane < M_) s_knet[N_ + lane] = dx * inv2;
            }
            __syncthreads();
            // l1 = relu(W1 @ knet + b1)   (thread-per-row, 52-wide)
            for (int r = tid; r < H1_; r += NTHR) {
                const float4* w4 = (const float4*)(W1 + (size_t)r * DIN);
                const float4* k4 = (const float4*)s_knet;
                float acc = b1[r];
#pragma unroll
                for (int c = 0; c < DIN / 4; ++c) {
                    float4 a = w4[c], b = k4[c];
                    acc = fmaf(a.x, b.x, acc);
                    acc = fmaf(a.y, b.y, acc);
                    acc = fmaf(a.z, b.z, acc);
                    acc = fmaf(a.w, b.w, acc);
                }
                g_l1[r] = fmaxf(acc, 0.f);
            }
        }
        grid_barrier();

        // ================= Phase 2: gi = Wih @ l1 + bih =================
        for (int i = tid; i < H1_; i += NTHR) s_vec[i] = g_l1[i];
        __syncthreads();
        {
            int gw = bid * NWARP + wid;
            for (int r = gw; r < G3_; r += NBLK * NWARP) {
                float v = warp_dot(Wih + (size_t)r * H1_, s_vec, H1_ / 4);
                if (lane == 0) g_gi[r] = v + bih[r];
            }
        }
        grid_barrier();

        // ================= Phase 3: gates (redundant) + l2 =================
        for (int i = tid; i < HID_; i += NTHR) {
            float hold = hsrc[i];
            float ir = g_gi[i], iz = g_gi[i + HID_], in_ = g_gi[i + 2 * HID_];
            float hr = g_gh[i], hz = g_gh[i + HID_], hn  = g_gh[i + 2 * HID_];
            float rg = sigmoidf_(ir + hr);
            float zg = sigmoidf_(iz + hz);
            float ng = tanhf(in_ + rg * hn);
            s_h[i] = (1.f - zg) * ng + zg * hold;
        }
        __syncthreads();
        {
            int gw = bid * NWARP + wid;
            for (int r = gw; r < H2_; r += NBLK * NWARP) {
                float v = warp_dot(W2 + (size_t)r * HID_, s_h, HID_ / 4);
                if (lane == 0) g_l2[r] = fmaxf(v + b2[r], 0.f);
            }
        }
        if (bid == 0) {
            float* hd = g_h[(t + 1) & 1];
            for (int i = tid; i < HID_; i += NTHR) hd[i] = s_h[i];
        }
        grid_barrier();
    }

    // ================= epilogue: posterior for final step =================
    if (bid == 0) {
        for (int i = tid; i < H2_; i += NTHR) s_l2[i] = g_l2[i];
        if (tid < M_) s_xacc[tid] = 0.f;
        __syncthreads();
        for (int r = wid; r < M_ * N_; r += NWARP) {
            float v = warp_dot(W3 + (size_t)r * H2_, s_l2, H2_ / 4);
            if (lane == 0) {
                v = (v + b3[r]) * 1e-4f;
                atomicAdd(&s_xacc[r / N_], v * s_dy[r % N_]);
            }
        }
        __syncthreads();
        if (tid < M_) out[tid * T_LEN + (T_LEN - 1)] = s_xprior[tid] + s_xacc[tid];
    }
}

// ---------------- launch ---------------------------------------------------
extern "C" void kernel_launch(void* const* d_in, const int* in_sizes, int n_in,
                              void* d_out, int out_size) {
    const float* A    = (const float*)d_in[0];
    const float* C    = (const float*)d_in[1];
    const float* x0   = (const float*)d_in[2];
    const float* h0   = (const float*)d_in[3];
    const float* y    = (const float*)d_in[4];
    const float* W1   = (const float*)d_in[5];
    const float* b1   = (const float*)d_in[6];
    const float* Wih  = (const float*)d_in[7];
    const float* Whh  = (const float*)d_in[8];
    const float* bih  = (const float*)d_in[9];
    const float* bhh  = (const float*)d_in[10];
    const float* W2   = (const float*)d_in[11];
    const float* b2   = (const float*)d_in[12];
    const float* W3   = (const float*)d_in[13];
    const float* b3   = (const float*)d_in[14];
    float* out = (float*)d_out;

    kalmannet_kernel<<<NBLK, NTHR>>>(A, C, x0, h0, y, W1, b1, Wih, Whh,
                                     bih, bhh, W2, b2, W3, b3, out);
}

// round 2
// speedup vs baseline: 1.8901x; 1.8901x over previous
#include <cuda_runtime.h>
#include <cuda_fp16.h>
#include <math.h>

// Problem dims
#define T_LEN 512
#define M_    4
#define N_    48
#define DIN   52          // M + N
#define H1_   4160
#define HID_  2320
#define G3_   6960        // 3 * HID
#define H2_   768
#define DOUT  192         // M * N

#define NBLK  148
#define NTHR  512
#define NWARP 16
#define WHH_BLKS 139      // blocks 1..139 do Whh in phase A
#define AUX_BLKS 8        // blocks 140..147 do z then W1 in phase A

// ---------------- device scratch (static: allocation-free) ----------------
__device__ __align__(16) __half w_ih_h[(size_t)G3_ * H1_];   // 57.9 MB
__device__ __align__(16) __half w_hh_h[(size_t)G3_ * HID_];  // 32.3 MB
__device__ __align__(16) __half w1_h[(size_t)H1_ * DIN];
__device__ __align__(16) __half w2_h[(size_t)H2_ * HID_];
__device__ __align__(16) __half w3_h[(size_t)DOUT * H2_];

__device__ __align__(16) float g_h[2][HID_];
__device__ __align__(16) float g_l1[H1_];
__device__ __align__(16) float g_gi[G3_];
__device__ __align__(16) float g_gh[G3_];
__device__ __align__(16) float g_l2[H2_];
__device__ __align__(16) float g_z[DOUT];     // (W3@l2 + b3) * 1e-4
__device__ __align__(16) float g_knet[DIN + 4];
__device__ unsigned g_bar_count;
__device__ unsigned g_bar_gen;
__device__ unsigned g_knet_flag;   // 0/1, reset each step in phase B
__device__ unsigned g_zdone;       // counts AUX blocks done with z, reset phase B

// ---------------- fp16 conversion kernel (runs every launch) --------------
__device__ __forceinline__ void cvt8(const float* __restrict__ src,
                                     __half* __restrict__ dst, size_t g) {
    const float4* s4 = (const float4*)src;
    float4 a = s4[2 * g], b = s4[2 * g + 1];
    __half2 h0 = __floats2half2_rn(a.x, a.y);
    __half2 h1 = __floats2half2_rn(a.z, a.w);
    __half2 h2 = __floats2half2_rn(b.x, b.y);
    __half2 h3 = __floats2half2_rn(b.z, b.w);
    uint4 o;
    o.x = *(unsigned*)&h0; o.y = *(unsigned*)&h1;
    o.z = *(unsigned*)&h2; o.w = *(unsigned*)&h3;
    ((uint4*)dst)[g] = o;
}

__global__ void cvt_kernel(const float* __restrict__ W1,
                           const float* __restrict__ Wih,
                           const float* __restrict__ Whh,
                           const float* __restrict__ W2,
                           const float* __restrict__ W3) {
    size_t i0 = (size_t)blockIdx.x * blockDim.x + threadIdx.x;
    size_t st = (size_t)gridDim.x * blockDim.x;
    const size_t nIH = (size_t)G3_ * H1_ / 8, nHH = (size_t)G3_ * HID_ / 8;
    const size_t n1 = (size_t)H1_ * DIN / 8, n2 = (size_t)H2_ * HID_ / 8;
    const size_t n3 = (size_t)DOUT * H2_ / 8;
    for (size_t g = i0; g < nIH; g += st) cvt8(Wih, w_ih_h, g);
    for (size_t g = i0; g < nHH; g += st) cvt8(Whh, w_hh_h, g);
    for (size_t g = i0; g < n1;  g += st) cvt8(W1, w1_h, g);
    for (size_t g = i0; g < n2;  g += st) cvt8(W2, w2_h, g);
    for (size_t g = i0; g < n3;  g += st) cvt8(W3, w3_h, g);
}

// ---------------- grid barrier --------------------------------------------
__device__ __forceinline__ void grid_barrier() {
    __threadfence();   // all threads: publish stores before arrival
    __syncthreads();
    if (threadIdx.x == 0) {
        unsigned gen = *((volatile unsigned*)&g_bar_gen);
        if (atomicAdd(&g_bar_count, 1u) == gridDim.x - 1u) {
            atomicExch(&g_bar_count, 0u);
            __threadfence();
            *((volatile unsigned*)&g_bar_gen) = gen + 1u;
        } else {
            while (*((volatile unsigned*)&g_bar_gen) == gen) { }
        }
        __threadfence();  // gpu-scope fence -> CCTL.IVALL (invalidate SM L1D)
    }
    __syncthreads();
}

// ---------------- warp dot: fp16 row (half8 lanes) vs fp32 smem vector -----
__device__ __forceinline__ float warp_dot_h8(const __half* __restrict__ w,
                                             const float* __restrict__ x,
                                             int n8) {
    const uint4* w4 = (const uint4*)w;
    const float4* x4 = (const float4*)x;
    int lane = threadIdx.x & 31;
    float acc = 0.f;
#pragma unroll 4
    for (int c = lane; c < n8; c += 32) {
        uint4 a = w4[c];
        float4 xa = x4[2 * c], xb = x4[2 * c + 1];
        float2 f;
        f = __half22float2(*(__half2*)&a.x);
        acc = fmaf(f.x, xa.x, acc); acc = fmaf(f.y, xa.y, acc);
        f = __half22float2(*(__half2*)&a.y);
        acc = fmaf(f.x, xa.z, acc); acc = fmaf(f.y, xa.w, acc);
        f = __half22float2(*(__half2*)&a.z);
        acc = fmaf(f.x, xb.x, acc); acc = fmaf(f.y, xb.y, acc);
        f = __half22float2(*(__half2*)&a.w);
        acc = fmaf(f.x, xb.z, acc); acc = fmaf(f.y, xb.w, acc);
    }
#pragma unroll
    for (int o = 16; o; o >>= 1) acc += __shfl_down_sync(0xffffffffu, acc, o);
    return acc;
}

__device__ __forceinline__ float sigmoidf_(float x) {
    return 1.f / (1.f + __expf(-x));
}

// ---------------- persistent kernel ---------------------------------------
__global__ void __launch_bounds__(NTHR, 1)
kalmannet_kernel(const float* __restrict__ A,   const float* __restrict__ C,
                 const float* __restrict__ x0,  const float* __restrict__ h0,
                 const float* __restrict__ y,   const float* __restrict__ b1,
                 const float* __restrict__ bih, const float* __restrict__ bhh,
                 const float* __restrict__ b2,  const float* __restrict__ b3,
                 float* __restrict__ out) {
    const int tid  = threadIdx.x;
    const int bid  = blockIdx.x;
    const int wid  = tid >> 5;
    const int lane = tid & 31;

    __shared__ __align__(16) float s_vec[H1_];   // l1 staging (phase B)
    __shared__ __align__(16) float s_h[HID_];    // h staging / h_new
    __shared__ __align__(16) float s_l2[H2_];    // aux blocks + epilogue
    __shared__ __align__(16) float s_z[DOUT];    // block 0
    __shared__ __align__(16) float s_knet[DIN + 4];
    __shared__ float s_dy[N_];                   // block 0, persists across steps
    __shared__ float s_xprior[M_], s_xpost[M_], s_xprev[M_];

    for (int t = 0; t < T_LEN; ++t) {
        const float* hsrc = (t == 0) ? h0 : g_h[t & 1];

        // ======================= Phase A =======================
        if (bid == 0) {
            // ---- serial chain ----
            if (t == 0) {
                if (tid < M_) { s_xpost[tid] = x0[tid]; s_xprev[tid] = x0[tid]; }
                __syncthreads();
            } else {
                if (tid == 0) {
                    while (*((volatile unsigned*)&g_zdone) != AUX_BLKS) { }
                    __threadfence();
                }
                __syncthreads();
                if (tid < DOUT) s_z[tid] = g_z[tid];
                __syncthreads();
                if (tid < M_) {
                    float acc = 0.f;
#pragma unroll 4
                    for (int j = 0; j < N_; ++j)
                        acc = fmaf(s_z[tid * N_ + j], s_dy[j], acc);
                    float xp = s_xprior[tid] + acc;
                    s_xprev[tid] = s_xprior[tid];
                    s_xpost[tid] = xp;
                    out[tid * T_LEN + (t - 1)] = xp;
                }
                __syncthreads();
            }
            // x_prior = A @ x_post
            if (tid < M_) {
                float acc = 0.f;
#pragma unroll
                for (int k = 0; k < M_; ++k) acc = fmaf(A[tid * M_ + k], s_xpost[k], acc);
                s_xprior[tid] = acc;
            }
            __syncthreads();
            // dy, dx, normalized knet (warp 0)
            if (wid == 0) {
                for (int j = lane; j < N_; j += 32) {
                    float m = C[j * (M_ + 1) + M_];
#pragma unroll
                    for (int k = 0; k < M_; ++k) m = fmaf(C[j * (M_ + 1) + k], s_xprior[k], m);
                    s_dy[j] = y[j * T_LEN + t] - m;
                }
                __syncwarp();
                float sq = 0.f;
                for (int j = lane; j < N_; j += 32) sq += s_dy[j] * s_dy[j];
#pragma unroll
                for (int o = 16; o; o >>= 1) sq += __shfl_down_sync(0xffffffffu, sq, o);
                sq = __shfl_sync(0xffffffffu, sq, 0);
                float inv = 1.f / fmaxf(sqrtf(sq), 1e-12f);
                for (int j = lane; j < N_; j += 32) g_knet[j] = s_dy[j] * inv;

                float dx = (lane < M_) ? (s_xpost[lane] - s_xprev[lane]) : 0.f;
                float sq2 = dx * dx;
#pragma unroll
                for (int o = 16; o; o >>= 1) sq2 += __shfl_down_sync(0xffffffffu, sq2, o);
                sq2 = __shfl_sync(0xffffffffu, sq2, 0);
                float inv2 = 1.f / fmaxf(sqrtf(sq2), 1e-12f);
                if (lane < M_) g_knet[N_ + lane] = dx * inv2;
                __syncwarp();
                if (lane == 0) {
                    __threadfence();
                    *((volatile unsigned*)&g_knet_flag) = 1u;
                }
            }
        } else if (bid <= WHH_BLKS) {
            // ---- gh = Whh @ h + bhh ----
            for (int i = tid; i < HID_; i += NTHR) s_h[i] = hsrc[i];
            __syncthreads();
            int gw = (bid - 1) * NWARP + wid;
            for (int r = gw; r < G3_; r += WHH_BLKS * NWARP) {
                float v = warp_dot_h8(w_hh_h + (size_t)r * HID_, s_h, HID_ / 8);
                if (lane == 0) g_gh[r] = v + bhh[r];
            }
        } else {
            // ---- aux blocks: z = (W3@l2 + b3)*1e-4, then l1 = relu(W1@knet+b1)
            int ab = bid - (WHH_BLKS + 1);   // 0..7
            if (t > 0) {
                for (int i = tid; i < H2_; i += NTHR) s_l2[i] = g_l2[i];
                __syncthreads();
                for (int r = ab * (DOUT / AUX_BLKS) + wid;
                     r < (ab + 1) * (DOUT / AUX_BLKS); r += NWARP) {
                    float v = warp_dot_h8(w3_h + (size_t)r * H2_, s_l2, H2_ / 8);
                    if (lane == 0) g_z[r] = (v + b3[r]) * 1e-4f;
                }
                __threadfence();
                __syncthreads();
                if (tid == 0) atomicAdd(&g_zdone, 1u);
            }
            if (tid == 0) {
                while (*((volatile unsigned*)&g_knet_flag) == 0u) { }
                __threadfence();
            }
            __syncthreads();
            if (tid < DIN) s_knet[tid] = g_knet[tid];
            __syncthreads();
            int gtid = ab * NTHR + tid;
            for (int r = gtid; r < H1_; r += AUX_BLKS * NTHR) {
                const __half2* wp = (const __half2*)(w1_h + (size_t)r * DIN);
                float acc = b1[r];
#pragma unroll
                for (int c = 0; c < DIN / 2; ++c) {
                    float2 f = __half22float2(wp[c]);
                    acc = fmaf(f.x, s_knet[2 * c], acc);
                    acc = fmaf(f.y, s_knet[2 * c + 1], acc);
                }
                g_l1[r] = fmaxf(acc, 0.f);
            }
        }
        grid_barrier();

        // ======================= Phase B: gi = Wih @ l1 + bih ==============
        if (bid == 0 && tid == 0) { g_knet_flag = 0u; g_zdone = 0u; }
        for (int i = tid; i < H1_; i += NTHR) s_vec[i] = g_l1[i];
        __syncthreads();
        {
            int gw = bid * NWARP + wid;
            for (int r = gw; r < G3_; r += NBLK * NWARP) {
                float v = warp_dot_h8(w_ih_h + (size_t)r * H1_, s_vec, H1_ / 8);
                if (lane == 0) g_gi[r] = v + bih[r];
            }
        }
        grid_barrier();

        // ======================= Phase C: gates + l2 =======================
        for (int i = tid; i < HID_; i += NTHR) {
            float hold = hsrc[i];
            float rg = sigmoidf_(g_gi[i] + g_gh[i]);
            float zg = sigmoidf_(g_gi[i + HID_] + g_gh[i + HID_]);
            float ng = tanhf(g_gi[i + 2 * HID_] + rg * g_gh[i + 2 * HID_]);
            s_h[i] = (1.f - zg) * ng + zg * hold;
        }
        __syncthreads();
        {
            int gw = bid * NWARP + wid;
            for (int r = gw; r < H2_; r += NBLK * NWARP) {
                float v = warp_dot_h8(w2_h + (size_t)r * HID_, s_h, HID_ / 8);
                if (lane == 0) g_l2[r] = fmaxf(v + b2[r], 0.f);
            }
        }
        if (bid == 0) {
            float* hd = g_h[(t + 1) & 1];
            for (int i = tid; i < HID_; i += NTHR) hd[i] = s_h[i];
        }
        grid_barrier();
    }

    // ================= epilogue: posterior for final step ==================
    if (bid == 0) {
        for (int i = tid; i < H2_; i += NTHR) s_l2[i] = g_l2[i];
        __syncthreads();
        for (int r = wid; r < DOUT; r += NWARP) {
            float v = warp_dot_h8(w3_h + (size_t)r * H2_, s_l2, H2_ / 8);
            if (lane == 0) s_z[r] = (v + b3[r]) * 1e-4f;
        }
        __syncthreads();
        if (tid < M_) {
            float acc = 0.f;
#pragma unroll 4
            for (int j = 0; j < N_; ++j) acc = fmaf(s_z[tid * N_ + j], s_dy[j], acc);
            out[tid * T_LEN + (T_LEN - 1)] = s_xprior[tid] + acc;
        }
    }
}

// ---------------- launch ---------------------------------------------------
extern "C" void kernel_launch(void* const* d_in, const int* in_sizes, int n_in,
                              void* d_out, int out_size) {
    const float* A    = (const float*)d_in[0];
    const float* C    = (const float*)d_in[1];
    const float* x0   = (const float*)d_in[2];
    const float* h0   = (const float*)d_in[3];
    const float* y    = (const float*)d_in[4];
    const float* W1   = (const float*)d_in[5];
    const float* b1   = (const float*)d_in[6];
    const float* Wih  = (const float*)d_in[7];
    const float* Whh  = (const float*)d_in[8];
    const float* bih  = (const float*)d_in[9];
    const float* bhh  = (const float*)d_in[10];
    const float* W2   = (const float*)d_in[11];
    const float* b2   = (const float*)d_in[12];
    const float* W3   = (const float*)d_in[13];
    const float* b3   = (const float*)d_in[14];
    float* out = (float*)d_out;

    cvt_kernel<<<2048, 256>>>(W1, Wih, Whh, W2, W3);
    kalmannet_kernel<<<NBLK, NTHR>>>(A, C, x0, h0, y, b1, bih, bhh, b2, b3, out);
}

// round 3
// speedup vs baseline: 1.9618x; 1.0380x over previous
#include <cuda_runtime.h>
#include <cuda_fp16.h>
#include <math.h>

// Problem dims
#define T_LEN 512
#define M_    4
#define N_    48
#define DIN   52          // M + N
#define H1_   4160
#define HID_  2320
#define G3_   6960        // 3 * HID
#define H2_   768
#define DOUT  192         // M * N

#define NBLK  148
#define NTHR  512
#define NWARP 16

// block roles in phase A
#define W2_B0   1
#define W2_NB   16        // blocks 1..16: W2 rows (48 each)
#define AUX_B0  17
#define AUX_NB  8         // blocks 17..24: l1 = relu(W1@knet)
#define WHH_B0  25
#define WHH_NB  123       // blocks 25..147: Whh

// ---------------- device scratch (static: allocation-free) ----------------
__device__ __align__(16) __half w_ih_h[(size_t)G3_ * H1_];   // 57.9 MB
__device__ __align__(16) __half w_hh_h[(size_t)G3_ * HID_];  // 32.3 MB
__device__ __align__(16) __half w2_h[(size_t)H2_ * HID_];    // 3.6 MB

__device__ __align__(16) float  g_h[2][HID_];    // fp32 hidden state
__device__ __align__(16) __half g_hh[2][HID_];   // fp16 copy for matvecs
__device__ __align__(16) __half g_l1h[H1_];      // l1 as half
__device__ __align__(16) float  g_gh[G3_];
__device__ __align__(16) float  g_l2[H2_];
__device__ __align__(16) float  g_knet[DIN + 4];
__device__ unsigned g_bar_count;
__device__ unsigned g_bar_gen;
__device__ unsigned g_knet_flag;
__device__ unsigned g_l2done;

// ---------------- fp16 conversion kernel ----------------------------------
__device__ __forceinline__ void cvt8(const float* __restrict__ src,
                                     __half* __restrict__ dst, size_t g) {
    const float4* s4 = (const float4*)src;
    float4 a = s4[2 * g], b = s4[2 * g + 1];
    __half2 h0 = __floats2half2_rn(a.x, a.y);
    __half2 h1 = __floats2half2_rn(a.z, a.w);
    __half2 h2 = __floats2half2_rn(b.x, b.y);
    __half2 h3 = __floats2half2_rn(b.z, b.w);
    uint4 o;
    o.x = *(unsigned*)&h0; o.y = *(unsigned*)&h1;
    o.z = *(unsigned*)&h2; o.w = *(unsigned*)&h3;
    ((uint4*)dst)[g] = o;
}

__global__ void cvt_kernel(const float* __restrict__ Wih,
                           const float* __restrict__ Whh,
                           const float* __restrict__ W2) {
    size_t i0 = (size_t)blockIdx.x * blockDim.x + threadIdx.x;
    size_t st = (size_t)gridDim.x * blockDim.x;
    const size_t nIH = (size_t)G3_ * H1_ / 8, nHH = (size_t)G3_ * HID_ / 8;
    const size_t n2 = (size_t)H2_ * HID_ / 8;
    for (size_t g = i0; g < nIH; g += st) cvt8(Wih, w_ih_h, g);
    for (size_t g = i0; g < nHH; g += st) cvt8(Whh, w_hh_h, g);
    for (size_t g = i0; g < n2;  g += st) cvt8(W2, w2_h, g);
}

// ---------------- grid barrier --------------------------------------------
__device__ __forceinline__ void grid_barrier() {
    __threadfence();
    __syncthreads();
    if (threadIdx.x == 0) {
        unsigned gen = *((volatile unsigned*)&g_bar_gen);
        if (atomicAdd(&g_bar_count, 1u) == gridDim.x - 1u) {
            atomicExch(&g_bar_count, 0u);
            __threadfence();
            *((volatile unsigned*)&g_bar_gen) = gen + 1u;
        } else {
            while (*((volatile unsigned*)&g_bar_gen) == gen) { }
        }
        __threadfence();  // acquire: invalidate L1D
    }
    __syncthreads();
}

// ---------------- warp dot: half weights x half2 smem vector ---------------
// 4 independent half2 accumulators -> no serial FMA chain, no converts.
__device__ __forceinline__ float warp_dot_hh(const __half* __restrict__ w,
                                             const uint4* __restrict__ xs,
                                             int n8) {
    const uint4* w4 = (const uint4*)w;
    int lane = threadIdx.x & 31;
    __half2 a0 = __float2half2_rn(0.f), a1 = a0, a2 = a0, a3 = a0;
#pragma unroll 4
    for (int c = lane; c < n8; c += 32) {
        uint4 wv = w4[c];
        uint4 xv = xs[c];
        a0 = __hfma2(*(__half2*)&wv.x, *(__half2*)&xv.x, a0);
        a1 = __hfma2(*(__half2*)&wv.y, *(__half2*)&xv.y, a1);
        a2 = __hfma2(*(__half2*)&wv.z, *(__half2*)&xv.z, a2);
        a3 = __hfma2(*(__half2*)&wv.w, *(__half2*)&xv.w, a3);
    }
    float2 f0 = __half22float2(a0), f1 = __half22float2(a1);
    float2 f2 = __half22float2(a2), f3 = __half22float2(a3);
    float acc = ((f0.x + f0.y) + (f1.x + f1.y)) + ((f2.x + f2.y) + (f3.x + f3.y));
#pragma unroll
    for (int o = 16; o; o >>= 1) acc += __shfl_down_sync(0xffffffffu, acc, o);
    return acc;
}

// fp32 warp dot (for W3, small + precision-sensitive)
__device__ __forceinline__ float warp_dot_f(const float* __restrict__ w,
                                            const float* __restrict__ x,
                                            int n4) {
    const float4* w4 = (const float4*)w;
    const float4* x4 = (const float4*)x;
    int lane = threadIdx.x & 31;
    float acc0 = 0.f, acc1 = 0.f, acc2 = 0.f, acc3 = 0.f;
#pragma unroll 4
    for (int c = lane; c < n4; c += 32) {
        float4 a = w4[c], b = x4[c];
        acc0 = fmaf(a.x, b.x, acc0);
        acc1 = fmaf(a.y, b.y, acc1);
        acc2 = fmaf(a.z, b.z, acc2);
        acc3 = fmaf(a.w, b.w, acc3);
    }
    float acc = (acc0 + acc1) + (acc2 + acc3);
#pragma unroll
    for (int o = 16; o; o >>= 1) acc += __shfl_down_sync(0xffffffffu, acc, o);
    return acc;
}

__device__ __forceinline__ float sigmoidf_(float x) {
    return 1.f / (1.f + __expf(-x));
}

// stage hidden state (half2) into smem
__device__ __forceinline__ void stage_h_half(uint4* s_x, int t, int hb,
                                             const float* __restrict__ h0) {
    if (t == 0) {
        for (int i = threadIdx.x; i < HID_ / 2; i += NTHR) {
            float2 f = ((const float2*)h0)[i];
            ((__half2*)s_x)[i] = __floats2half2_rn(f.x, f.y);
        }
    } else {
        const uint4* src = (const uint4*)g_hh[hb];
        for (int i = threadIdx.x; i < HID_ / 8; i += NTHR) s_x[i] = src[i];
    }
    __syncthreads();
}

// ---------------- persistent kernel ---------------------------------------
__global__ void __launch_bounds__(NTHR, 1)
kalmannet_kernel(const float* __restrict__ A,   const float* __restrict__ C,
                 const float* __restrict__ x0,  const float* __restrict__ h0,
                 const float* __restrict__ y,   const float* __restrict__ W1,
                 const float* __restrict__ b1,  const float* __restrict__ bih,
                 const float* __restrict__ bhh, const float* __restrict__ b2,
                 const float* __restrict__ W3,  const float* __restrict__ b3,
                 float* __restrict__ out) {
    const int tid  = threadIdx.x;
    const int bid  = blockIdx.x;
    const int wid  = tid >> 5;
    const int lane = tid & 31;

    __shared__ __align__(16) uint4 s_x[H1_ / 8];     // 8320B: h(half2) in A, l1(half2) in B
    __shared__ __align__(16) float s_l2f[H2_];       // block 0: l2 fp32
    __shared__ __align__(16) float s_z[DOUT];
    __shared__ __align__(16) float s_knet[DIN + 4];
    __shared__ float s_dy[N_];
    __shared__ float s_xprior[M_], s_xpost[M_], s_xprev[M_];

    for (int t = 0; t < T_LEN; ++t) {
        const int hb = (t & 1) ^ 1;   // buffer holding h(t-1)

        // ======================= Phase A =======================
        if (bid == 0) {
            // ---- serial chain ----
            if (t == 0) {
                if (tid < M_) { s_xpost[tid] = x0[tid]; s_xprev[tid] = x0[tid]; }
                __syncthreads();
            } else {
                if (tid == 0) {
                    while (*((volatile unsigned*)&g_l2done) != W2_NB) { }
                    __threadfence();
                }
                __syncthreads();
                for (int i = tid; i < H2_; i += NTHR) s_l2f[i] = g_l2[i];
                __syncthreads();
                // z = (W3 @ l2 + b3) * 1e-4   (fp32, 12 rows/warp)
                for (int r = wid; r < DOUT; r += NWARP) {
                    float v = warp_dot_f(W3 + (size_t)r * H2_, s_l2f, H2_ / 4);
                    if (lane == 0) s_z[r] = (v + b3[r]) * 1e-4f;
                }
                __syncthreads();
                if (tid < M_) {
                    float acc = 0.f;
#pragma unroll 4
                    for (int j = 0; j < N_; ++j)
                        acc = fmaf(s_z[tid * N_ + j], s_dy[j], acc);
                    float xp = s_xprior[tid] + acc;
                    s_xprev[tid] = s_xprior[tid];
                    s_xpost[tid] = xp;
                    out[tid * T_LEN + (t - 1)] = xp;
                }
                __syncthreads();
            }
            // x_prior = A @ x_post
            if (tid < M_) {
                float acc = 0.f;
#pragma unroll
                for (int k = 0; k < M_; ++k) acc = fmaf(A[tid * M_ + k], s_xpost[k], acc);
                s_xprior[tid] = acc;
            }
            __syncthreads();
            // dy, dx, normalized knet (warp 0)
            if (wid == 0) {
                for (int j = lane; j < N_; j += 32) {
                    float m = C[j * (M_ + 1) + M_];
#pragma unroll
                    for (int k = 0; k < M_; ++k) m = fmaf(C[j * (M_ + 1) + k], s_xprior[k], m);
                    s_dy[j] = y[j * T_LEN + t] - m;
                }
                __syncwarp();
                float sq = 0.f;
                for (int j = lane; j < N_; j += 32) sq += s_dy[j] * s_dy[j];
#pragma unroll
                for (int o = 16; o; o >>= 1) sq += __shfl_down_sync(0xffffffffu, sq, o);
                sq = __shfl_sync(0xffffffffu, sq, 0);
                float inv = 1.f / fmaxf(sqrtf(sq), 1e-12f);
                for (int j = lane; j < N_; j += 32) g_knet[j] = s_dy[j] * inv;

                float dx = (lane < M_) ? (s_xpost[lane] - s_xprev[lane]) : 0.f;
                float sq2 = dx * dx;
#pragma unroll
                for (int o = 16; o; o >>= 1) sq2 += __shfl_down_sync(0xffffffffu, sq2, o);
                sq2 = __shfl_sync(0xffffffffu, sq2, 0);
                float inv2 = 1.f / fmaxf(sqrtf(sq2), 1e-12f);
                if (lane < M_) g_knet[N_ + lane] = dx * inv2;
                __syncwarp();
                if (lane == 0) {
                    __threadfence();
                    atomicExch(&g_knet_flag, 1u);
                }
            }
        } else if (bid < AUX_B0) {
            // ---- W2 blocks: l2 = relu(W2 @ h(t-1) + b2), 48 rows each ----
            if (t > 0) {
                stage_h_half(s_x, t, hb, h0);
                int r0 = (bid - W2_B0) * (H2_ / W2_NB);
                for (int r = r0 + wid; r < r0 + H2_ / W2_NB; r += NWARP) {
                    float v = warp_dot_hh(w2_h + (size_t)r * HID_, s_x, HID_ / 8);
                    if (lane == 0) g_l2[r] = fmaxf(v + b2[r], 0.f);
                }
                __threadfence();
                __syncthreads();
                if (tid == 0) atomicAdd(&g_l2done, 1u);
            }
        } else if (bid < WHH_B0) {
            // ---- aux blocks: l1 = relu(W1 @ knet + b1)  (fp32 weights) ----
            int ab = bid - AUX_B0;
            if (tid == 0) {
                while (*((volatile unsigned*)&g_knet_flag) == 0u) { }
                __threadfence();
            }
            __syncthreads();
            if (tid < DIN) s_knet[tid] = g_knet[tid];
            __syncthreads();
            for (int r = ab * NTHR + tid; r < H1_; r += AUX_NB * NTHR) {
                const float4* w4 = (const float4*)(W1 + (size_t)r * DIN);
                const float4* k4 = (const float4*)s_knet;
                float acc = b1[r];
#pragma unroll
                for (int c = 0; c < DIN / 4; ++c) {
                    float4 a = w4[c], b = k4[c];
                    acc = fmaf(a.x, b.x, acc);
                    acc = fmaf(a.y, b.y, acc);
                    acc = fmaf(a.z, b.z, acc);
                    acc = fmaf(a.w, b.w, acc);
                }
                g_l1h[r] = __float2half(fmaxf(acc, 0.f));
            }
        } else {
            // ---- Whh blocks: gh = Whh @ h(t-1) + bhh ----
            stage_h_half(s_x, t, hb, h0);
            int gw = (bid - WHH_B0) * NWARP + wid;
            for (int r = gw; r < G3_; r += WHH_NB * NWARP) {
                float v = warp_dot_hh(w_hh_h + (size_t)r * HID_, s_x, HID_ / 8);
                if (lane == 0) g_gh[r] = v + bhh[r];
            }
        }
        grid_barrier();

        // ============ Phase B: gi rows + GRU gate, fused ============
        if (bid == 0 && tid == 0) { g_knet_flag = 0u; g_l2done = 0u; }
        {
            const uint4* src = (const uint4*)g_l1h;
            for (int i = tid; i < H1_ / 8; i += NTHR) s_x[i] = src[i];
        }
        __syncthreads();
        {
            int i0 = (bid * HID_) / NBLK;
            int i1 = ((bid + 1) * HID_) / NBLK;
            for (int i = i0 + wid; i < i1; i += NWARP) {
                float gr = warp_dot_hh(w_ih_h + (size_t)i * H1_, s_x, H1_ / 8);
                float gz = warp_dot_hh(w_ih_h + (size_t)(i + HID_) * H1_, s_x, H1_ / 8);
                float gn = warp_dot_hh(w_ih_h + (size_t)(i + 2 * HID_) * H1_, s_x, H1_ / 8);
                if (lane == 0) {
                    float hold = (t == 0) ? h0[i] : g_h[hb][i];
                    float rg = sigmoidf_(gr + bih[i] + g_gh[i]);
                    float zg = sigmoidf_(gz + bih[i + HID_] + g_gh[i + HID_]);
                    float ng = tanhf(gn + bih[i + 2 * HID_] + rg * g_gh[i + 2 * HID_]);
                    float hv = (1.f - zg) * ng + zg * hold;
                    g_h[t & 1][i] = hv;
                    g_hh[t & 1][i] = __float2half(hv);
                }
            }
        }
        grid_barrier();
    }

    // ================= epilogue: final posterior ==========================
    const int hbF = (T_LEN - 1) & 1;
    if (bid >= W2_B0 && bid < AUX_B0) {
        // W2 blocks: l2(T-1)
        {
            const uint4* src = (const uint4*)g_hh[hbF];
            for (int i = tid; i < HID_ / 8; i += NTHR) s_x[i] = src[i];
        }
        __syncthreads();
        int r0 = (bid - W2_B0) * (H2_ / W2_NB);
        for (int r = r0 + wid; r < r0 + H2_ / W2_NB; r += NWARP) {
            float v = warp_dot_hh(w2_h + (size_t)r * HID_, s_x, HID_ / 8);
            if (lane == 0) g_l2[r] = fmaxf(v + b2[r], 0.f);
        }
        __threadfence();
        __syncthreads();
        if (tid == 0) atomicAdd(&g_l2done, 1u);
    } else if (bid == 0) {
        if (tid == 0) {
            while (*((volatile unsigned*)&g_l2done) != W2_NB) { }
            __threadfence();
        }
        __syncthreads();
        for (int i = tid; i < H2_; i += NTHR) s_l2f[i] = g_l2[i];
        __syncthreads();
        for (int r = wid; r < DOUT; r += NWARP) {
            float v = warp_dot_f(W3 + (size_t)r * H2_, s_l2f, H2_ / 4);
            if (lane == 0) s_z[r] = (v + b3[r]) * 1e-4f;
        }
        __syncthreads();
        if (tid < M_) {
            float acc = 0.f;
#pragma unroll 4
            for (int j = 0; j < N_; ++j) acc = fmaf(s_z[tid * N_ + j], s_dy[j], acc);
            out[tid * T_LEN + (T_LEN - 1)] = s_xprior[tid] + acc;
        }
        __syncthreads();
        if (tid == 0) atomicExch(&g_l2done, 0u);   // reset for next launch/replay
    }
}

// ---------------- launch ---------------------------------------------------
extern "C" void kernel_launch(void* const* d_in, const int* in_sizes, int n_in,
                              void* d_out, int out_size) {
    const float* A    = (const float*)d_in[0];
    const float* C    = (const float*)d_in[1];
    const float* x0   = (const float*)d_in[2];
    const float* h0   = (const float*)d_in[3];
    const float* y    = (const float*)d_in[4];
    const float* W1   = (const float*)d_in[5];
    const float* b1   = (const float*)d_in[6];
    const float* Wih  = (const float*)d_in[7];
    const float* Whh  = (const float*)d_in[8];
    const float* bih  = (const float*)d_in[9];
    const float* bhh  = (const float*)d_in[10];
    const float* W2   = (const float*)d_in[11];
    const float* b2   = (const float*)d_in[12];
    const float* W3   = (const float*)d_in[13];
    const float* b3   = (const float*)d_in[14];
    float* out = (float*)d_out;

    cvt_kernel<<<2048, 256>>>(Wih, Whh, W2);
    kalmannet_kernel<<<NBLK, NTHR>>>(A, C, x0, h0, y, W1, b1, bih, bhh,
                                     b2, W3, b3, out);
}